// round 7
// baseline (speedup 1.0000x reference)
#include <cuda_runtime.h>
#include <cuda_fp16.h>
#include <cstdint>

// ============================================================================
// Problem constants
// ============================================================================
#define DGRID 128
#define D3 (DGRID * DGRID * DGRID)
#define MCAP 100096              // capacity (multiple of 128) >= M
#define NCH 64
#define WELEMS (27 * NCH * NCH)  // per-layer weight elems

// ============================================================================
// Device globals (scratch — no allocation allowed)
// ============================================================================
__device__ int g_lookup[D3];
__device__ int g_nbr[27 * MCAP];
__device__ __align__(16) __half g_xq[(MCAP + 1) * NCH];   // fp16(x), row M = 0
__device__ __align__(16) __half g_hx[(MCAP + 1) * NCH];   // fp16(h), row M = 0
__device__ __align__(16) __half g_wh[2 * WELEMS];         // fp16 hi of W^T, both layers
__device__ __align__(16) __half g_wl[2 * WELEMS];         // fp16 residual of W^T

// ============================================================================
// PTX helpers (baseline PTX only — sm_103a-only ops don't pass compute_103)
// ============================================================================
__device__ __forceinline__ uint32_t sw128(uint32_t off) {
    return off ^ ((off >> 3) & 0x70);
}

__device__ __forceinline__ void cp16(uint32_t smem_addr, const void* gptr) {
    asm volatile("cp.async.cg.shared.global [%0], [%1], 16;"
                 :: "r"(smem_addr), "l"(__cvta_generic_to_global(gptr)));
}

#define CP_COMMIT() asm volatile("cp.async.commit_group;" ::: "memory")
#define CP_WAIT(N)  asm volatile("cp.async.wait_group %0;" :: "n"(N) : "memory")

__device__ __forceinline__ void ldmat_x4(uint32_t* r, uint32_t addr) {
    asm volatile("ldmatrix.sync.aligned.m8n8.x4.shared.b16 {%0,%1,%2,%3}, [%4];"
                 : "=r"(r[0]), "=r"(r[1]), "=r"(r[2]), "=r"(r[3]) : "r"(addr));
}

__device__ __forceinline__ void mma_fp16(float* d, const uint32_t* a,
                                         uint32_t b0, uint32_t b1) {
    asm volatile(
        "mma.sync.aligned.m16n8k16.row.col.f32.f16.f16.f32 "
        "{%0,%1,%2,%3}, {%4,%5,%6,%7}, {%8,%9}, {%0,%1,%2,%3};"
        : "+f"(d[0]), "+f"(d[1]), "+f"(d[2]), "+f"(d[3])
        : "r"(a[0]), "r"(a[1]), "r"(a[2]), "r"(a[3]), "r"(b0), "r"(b1));
}

// ============================================================================
// Prep kernels
// ============================================================================
__global__ void k_convert_x(const float* __restrict__ feats, int M) {
    int idx = blockIdx.x * blockDim.x + threadIdx.x;
    if (idx >= (M + 1) * NCH) return;
    float v = (idx < M * NCH) ? feats[idx] : 0.0f;
    g_xq[idx] = __float2half(v);
    if (idx >= M * NCH) g_hx[idx] = __float2half(0.0f);  // zero row M of h
}

// W[t][j][c] (f32) -> W^T[t][c][j] fp16 hi + residual, both layers in one kernel
__global__ void k_convert_w(const float* __restrict__ W1,
                            const float* __restrict__ W2) {
    int idx = blockIdx.x * blockDim.x + threadIdx.x;
    if (idx >= 2 * WELEMS) return;
    int L = (idx >= WELEMS) ? 1 : 0;
    int r2 = idx - L * WELEMS;
    int t = r2 >> 12;
    int c = (r2 & 4095) >> 6;  // n (output channel)
    int j = r2 & 63;           // k (input channel)
    const float* W = L ? W2 : W1;
    float w = W[(t << 12) + (j << 6) + c];
    __half h = __float2half(w);
    __half l = __float2half(w - __half2float(h));
    g_wh[idx] = h;
    g_wl[idx] = l;
}

__global__ void k_init_lookup() {
    int i = blockIdx.x * blockDim.x + threadIdx.x;
    if (i < D3) g_lookup[i] = -1;
}

__global__ void k_scatter(const int* __restrict__ coords, int M) {
    int i = blockIdx.x * blockDim.x + threadIdx.x;
    if (i >= M) return;
    int c0 = coords[3 * i], c1 = coords[3 * i + 1], c2 = coords[3 * i + 2];
    g_lookup[(c0 * DGRID + c1) * DGRID + c2] = i;
}

__global__ void k_build_nbr(const int* __restrict__ coords, int M) {
    int i = blockIdx.x * blockDim.x + threadIdx.x;
    if (i >= M) return;
    int c0 = coords[3 * i], c1 = coords[3 * i + 1], c2 = coords[3 * i + 2];
#pragma unroll
    for (int t = 0; t < 27; t++) {
        int dx = t / 9 - 1, dy = (t / 3) % 3 - 1, dz = t % 3 - 1;
        int x = c0 + dx, y = c1 + dy, z = c2 + dz;
        int idx = M;  // zero row for invalid neighbors
        if (x >= 0 && x < DGRID && y >= 0 && y < DGRID && z >= 0 && z < DGRID) {
            int j = g_lookup[(x * DGRID + y) * DGRID + z];
            if (j >= 0) idx = j;
        }
        g_nbr[t * MCAP + i] = idx;
    }
}

// ============================================================================
// Conv layer kernel: fp16 2-term (x*Wh + x*Wl), 3-stage cp.async pipeline
// 128 rows x 64 cols per CTA, 256 threads (8 warps x 16 rows each)
// ============================================================================
#define SMEM_BIAS  0
#define SMEM_DATA  1024
#define A_OFF      0          // 16 KB: 128 rows x 128B (fp16 x)
#define WH_OFF     16384      // 8 KB: 64 rows x 128B
#define WL_OFF     24576      // 8 KB
#define STAGE      32768
#define SMEM_TOTAL (SMEM_DATA + 3 * STAGE)   // 99328 bytes -> 2 CTAs/SM

template <int LAYER>
__global__ void __launch_bounds__(256, 2)
conv_kernel(const float* __restrict__ bias, float* __restrict__ out, int M) {
    extern __shared__ __align__(1024) char smem[];
    const int tid  = threadIdx.x;
    const int warp = tid >> 5;
    const int lane = tid & 31;
    uint32_t sb;
    asm("{ .reg .u64 t; cvta.to.shared.u64 t, %1; cvt.u32.u64 %0, t; }"
        : "=r"(sb) : "l"(smem));

    const __half* __restrict__ Xq  = LAYER ? g_hx : g_xq;
    const __half* __restrict__ Wh0 = g_wh + LAYER * WELEMS;
    const __half* __restrict__ Wl0 = g_wl + LAYER * WELEMS;

    const int row0 = blockIdx.x * 128;
    if (tid < NCH) ((float*)(smem + SMEM_BIAS))[tid] = bias[tid];

    // ---- per-thread load geometry ----
    const int rr   = tid >> 1;           // A row (0..127)
    const int half = tid & 1;            // 64B half of the 128B row
    const int wc0  = tid * 2;            // W 16B-chunk base (2 per thread)
    const bool rvalid = (row0 + rr) < M;

    auto nbr_idx = [&](int k) -> int {
        return rvalid ? g_nbr[k * MCAP + row0 + rr] : M;
    };

    auto issue_load = [&](int k, uint32_t buf, int idx) {
        const char* src = (const char*)(Xq + (size_t)idx * NCH) + half * 64;
#pragma unroll
        for (int c = 0; c < 4; c++) {
            uint32_t so = sw128((uint32_t)(rr * 128 + half * 64 + c * 16));
            cp16(buf + A_OFF + so, src + c * 16);
        }
        const char* wsh = (const char*)(Wh0 + (size_t)k * 4096);
        const char* wsl = (const char*)(Wl0 + (size_t)k * 4096);
#pragma unroll
        for (int q = 0; q < 2; q++) {
            uint32_t off = (uint32_t)((wc0 + q) * 16);
            uint32_t so = sw128(off);
            cp16(buf + WH_OFF + so, wsh + off);
            cp16(buf + WL_OFF + so, wsl + off);
        }
    };

    float acc[8][4];

    // prologue: fill 3 stages
    issue_load(0, sb + SMEM_DATA + 0 * STAGE, nbr_idx(0));
    CP_COMMIT();
    issue_load(1, sb + SMEM_DATA + 1 * STAGE, nbr_idx(1));
    CP_COMMIT();
    issue_load(2, sb + SMEM_DATA + 2 * STAGE, nbr_idx(2));
    CP_COMMIT();
    int nidx = nbr_idx(3);
    __syncthreads();  // bias visible

    {
        const float* sbias = (const float*)(smem + SMEM_BIAS);
#pragma unroll
        for (int nt = 0; nt < 8; nt++) {
            int n = nt * 8 + (lane & 3) * 2;
            float b0 = sbias[n], b1 = sbias[n + 1];
            acc[nt][0] = b0; acc[nt][1] = b1; acc[nt][2] = b0; acc[nt][3] = b1;
        }
    }

    // ---- fragment address geometry ----
    const uint32_t a_row  = (uint32_t)(warp * 16 + (lane & 15));
    const uint32_t a_koff = (uint32_t)((lane >> 4) << 4);               // 0 / 16
    const uint32_t b_row  = (uint32_t)((lane & 7) + ((lane >> 4) << 3)); // 0..15
    const uint32_t b_koff = (uint32_t)(((lane >> 3) & 1) << 4);          // 0 / 16

    int stage = 0;
    for (int k = 0; k < 27; k++) {
        int nidx_next = (k + 4 < 27) ? nbr_idx(k + 4) : M;

        const uint32_t buf = sb + SMEM_DATA + (uint32_t)stage * STAGE;
        CP_WAIT(2);        // stage k's loads complete; 2 stages still in flight
        __syncthreads();

#pragma unroll
        for (int kk = 0; kk < 4; kk++) {
            uint32_t a[4];
            ldmat_x4(a, buf + A_OFF +
                        sw128(a_row * 128 + (uint32_t)kk * 32 + a_koff));
#pragma unroll
            for (int p = 0; p < 4; p++) {
                uint32_t so = sw128(((uint32_t)(p * 16) + b_row) * 128 +
                                    (uint32_t)kk * 32 + b_koff);
                uint32_t bh[4], bl[4];
                ldmat_x4(bh, buf + WH_OFF + so);
                ldmat_x4(bl, buf + WL_OFF + so);
                mma_fp16(acc[2 * p],     a, bh[0], bh[1]);
                mma_fp16(acc[2 * p + 1], a, bh[2], bh[3]);
                mma_fp16(acc[2 * p],     a, bl[0], bl[1]);
                mma_fp16(acc[2 * p + 1], a, bl[2], bl[3]);
            }
        }

        __syncthreads();   // all warps done reading this stage
        if (k + 3 < 27) issue_load(k + 3, buf, nidx);
        CP_COMMIT();       // uniform group accounting
        nidx = nidx_next;
        stage = (stage == 2) ? 0 : stage + 1;
    }

    // ---- epilogue: ReLU (bias already in acc), store ----
    const int m0 = row0 + warp * 16 + (lane >> 2);
    const int m1 = m0 + 8;
    if (LAYER == 0) {
        uint32_t* hp = (uint32_t*)g_hx;
#pragma unroll
        for (int nt = 0; nt < 8; nt++) {
            int n = nt * 8 + (lane & 3) * 2;
#pragma unroll
            for (int rp = 0; rp < 2; rp++) {
                int m = rp ? m1 : m0;
                if (m < M) {
                    float v0 = fmaxf(acc[nt][2 * rp],     0.0f);
                    float v1 = fmaxf(acc[nt][2 * rp + 1], 0.0f);
                    __half h0 = __float2half(v0);
                    __half h1 = __float2half(v1);
                    hp[m * 32 + n / 2] =
                        (uint32_t)__half_as_ushort(h0) |
                        ((uint32_t)__half_as_ushort(h1) << 16);
                }
            }
        }
    } else {
#pragma unroll
        for (int nt = 0; nt < 8; nt++) {
            int n = nt * 8 + (lane & 3) * 2;
#pragma unroll
            for (int rp = 0; rp < 2; rp++) {
                int m = rp ? m1 : m0;
                if (m < M) {
                    float2 v;
                    v.x = fmaxf(acc[nt][2 * rp],     0.0f);
                    v.y = fmaxf(acc[nt][2 * rp + 1], 0.0f);
                    *(float2*)(out + (size_t)m * NCH + n) = v;
                }
            }
        }
    }
}

// ============================================================================
// Launch — 7 kernels; conv0 at launch index 5 so ncu (-s 5 -c 1) captures it
// ============================================================================
extern "C" void kernel_launch(void* const* d_in, const int* in_sizes, int n_in,
                              void* d_out, int out_size) {
    const float* feats  = (const float*)d_in[0];
    const float* W1     = (const float*)d_in[1];
    const float* b1     = (const float*)d_in[2];
    const float* W2     = (const float*)d_in[3];
    const float* b2     = (const float*)d_in[4];
    const int*   coords = (const int*)d_in[5];
    const int M = in_sizes[0] / NCH;

    cudaFuncSetAttribute(conv_kernel<0>,
                         cudaFuncAttributeMaxDynamicSharedMemorySize, SMEM_TOTAL);
    cudaFuncSetAttribute(conv_kernel<1>,
                         cudaFuncAttributeMaxDynamicSharedMemorySize, SMEM_TOTAL);

    k_convert_x<<<((M + 1) * NCH + 255) / 256, 256>>>(feats, M);     // 0
    k_convert_w<<<(2 * WELEMS + 255) / 256, 256>>>(W1, W2);          // 1
    k_init_lookup<<<(D3 + 511) / 512, 512>>>();                      // 2
    k_scatter<<<(M + 255) / 256, 256>>>(coords, M);                  // 3
    k_build_nbr<<<(M + 255) / 256, 256>>>(coords, M);                // 4

    const int nblk = (M + 127) / 128;
    conv_kernel<0><<<nblk, 256, SMEM_TOTAL>>>(b1, nullptr, M);       // 5
    conv_kernel<1><<<nblk, 256, SMEM_TOTAL>>>(b2, (float*)d_out, M); // 6
}